// round 10
// baseline (speedup 1.0000x reference)
#include <cuda_runtime.h>
#include <cuda_fp16.h>
#include <cstdint>
#include <cstddef>

#define HEADS 32
#define HDIM  128
#define SEQL  4096
#define BLKS  256
#define NBLK  16
#define HID   4096
#define KDIM  4096

// fp16 operand buffers
__device__ __half g_xh[33554432];      // X           (b*s, 4096)
__device__ __half g_wqkvh[50331648];   // Wqkv        (12288, 4096)
__device__ __half g_wgh[16777216];     // Wg          (4096, 4096)
__device__ __half g_woh[16777216];     // Wo          (4096, 4096)
__device__ __half g_qh[33554432];      // (bh, s, d)
__device__ __half g_kh[33554432];
__device__ __half g_vh[33554432];
__device__ __half g_gated[33554432];   // sigmoid(gate)*normed (b*s, 4096)
// fp32 state
__device__ float  g_kv[16777216];      // (bh, blk, e, d)  [e-major = KV^T]
__device__ float  g_attn[33554432];    // (b, s, h*d)

__device__ __forceinline__ void mma16(float* c, const uint32_t* a, const uint32_t* b) {
    asm volatile("mma.sync.aligned.m16n8k16.row.col.f32.f16.f16.f32 "
        "{%0,%1,%2,%3},{%4,%5,%6,%7},{%8,%9},{%0,%1,%2,%3};\n"
        : "+f"(c[0]), "+f"(c[1]), "+f"(c[2]), "+f"(c[3])
        : "r"(a[0]), "r"(a[1]), "r"(a[2]), "r"(a[3]), "r"(b[0]), "r"(b[1]));
}
__device__ __forceinline__ float head_slope(int h) {
    float factor = 1.0f - 1.0f / (31.0f + 1e-5f) + 1e-5f;
    return exp2f(-0.25f * (float)(h + 1)) * factor;
}
__device__ __forceinline__ void cpa16(uint32_t dst, const void* src) {
    asm volatile("cp.async.cg.shared.global [%0], [%1], 16;" :: "r"(dst), "l"(src));
}
__device__ __forceinline__ uint32_t s2u(const void* p) {
    return (uint32_t)__cvta_generic_to_shared(p);
}

// ----------------------- fp32 -> fp16 conversion ---------------------------
template <int DST>
__global__ void __launch_bounds__(256) f2h(const float* __restrict__ s, int n4) {
    int i = blockIdx.x * 256 + threadIdx.x;
    if (i >= n4) return;
    float4 v = ((const float4*)s)[i];
    __half* d = (DST == 0) ? g_xh : (DST == 1) ? g_wqkvh : (DST == 2) ? g_wgh : g_woh;
    ((__half2*)d)[i * 2]     = __floats2half2_rn(v.x, v.y);
    ((__half2*)d)[i * 2 + 1] = __floats2half2_rn(v.z, v.w);
}

// ------------- fp16 NT GEMM: C[m,n] = sum_k A[m,k] B[n,k], K=4096 ----------
// cp.async 2-stage double-buffered pipeline.
// EPI 0: A=g_xh B=g_wqkvh, silu -> scatter q/k/v (half)
// EPI 1: A=g_xh B=g_wgh,   g_gated = half(sigmoid(C)*g_attn)
// EPI 2: A=g_gated B=g_woh, Cout = C (float)
#define GEMM_SMEM 73728   // 2 stages * (As 128x36 + Bs 128x36) words * 4B
template <int EPI>
__global__ void __launch_bounds__(256) gemm_h(float* __restrict__ Cout) {
    extern __shared__ uint32_t smg[];      // stage p: As at p*9216, Bs at p*9216+4608
    const int tid = threadIdx.x, lane = tid & 31, w = tid >> 5;
    const int wm = w & 1, wn = w >> 1;
    const int m0 = blockIdx.y * 128, n0 = blockIdx.x * 128;
    const __half* Ap = (EPI == 2) ? g_gated : g_xh;
    const __half* Bp = (EPI == 0) ? g_wqkvh : (EPI == 1) ? g_wgh : g_woh;
    const uint32_t smb = s2u(smg);

    const int lrow = tid >> 3;             // base row (stride 32 over 4 iters)
    const int lq   = tid & 7;              // 16B chunk within 64-half k-slab

    auto issue = [&](int kt, int p) {
        const size_t koff = (size_t)kt * 64 + lq * 8;
        const uint32_t ab = smb + p * 36864;            // As stage base (bytes)
        const uint32_t bbx = ab + 18432;                // Bs stage base
#pragma unroll
        for (int r = 0; r < 4; r++) {
            int row = lrow + 32 * r;
            cpa16(ab  + row * 144 + lq * 16, Ap + (size_t)(m0 + row) * KDIM + koff);
            cpa16(bbx + row * 144 + lq * 16, Bp + (size_t)(n0 + row) * KDIM + koff);
        }
        asm volatile("cp.async.commit_group;");
    };

    float acc[4][4][4];
#pragma unroll
    for (int i = 0; i < 4; i++)
#pragma unroll
        for (int j = 0; j < 4; j++)
#pragma unroll
            for (int r = 0; r < 4; r++) acc[i][j][r] = 0.f;

    issue(0, 0);
    const int NT = KDIM / 64;              // 64 k-tiles
    for (int kt = 0; kt < NT; kt++) {
        const int p = kt & 1;
        if (kt + 1 < NT) {
            issue(kt + 1, p ^ 1);
            asm volatile("cp.async.wait_group 1;");
        } else {
            asm volatile("cp.async.wait_group 0;");
        }
        __syncthreads();

        const uint32_t (*As)[36] = (const uint32_t(*)[36])(smg + p * 9216);
        const uint32_t (*Bs)[36] = (const uint32_t(*)[36])(smg + p * 9216 + 4608);
#pragma unroll
        for (int kk = 0; kk < 4; kk++) {
            const int kq = kk * 8 + (lane & 3);
            uint32_t a[4][4], bb[4][2];
#pragma unroll
            for (int mi = 0; mi < 4; mi++) {
                int r = wm * 64 + mi * 16 + (lane >> 2);
                a[mi][0] = As[r][kq];     a[mi][1] = As[r + 8][kq];
                a[mi][2] = As[r][kq + 4]; a[mi][3] = As[r + 8][kq + 4];
            }
#pragma unroll
            for (int ni = 0; ni < 4; ni++) {
                int c = wn * 32 + ni * 8 + (lane >> 2);
                bb[ni][0] = Bs[c][kq]; bb[ni][1] = Bs[c][kq + 4];
            }
#pragma unroll
            for (int mi = 0; mi < 4; mi++)
#pragma unroll
                for (int ni = 0; ni < 4; ni++) mma16(acc[mi][ni], a[mi], bb[ni]);
        }
        __syncthreads();
    }

#pragma unroll
    for (int mi = 0; mi < 4; mi++)
#pragma unroll
        for (int ni = 0; ni < 4; ni++)
#pragma unroll
            for (int r2 = 0; r2 < 4; r2++) {
                int row = m0 + wm * 64 + mi * 16 + (lane >> 2) + ((r2 >> 1) << 3);
                int col = n0 + wn * 32 + ni * 8 + ((lane & 3) << 1) + (r2 & 1);
                float v = acc[mi][ni][r2];
                if (EPI == 0) {
                    float sv = v / (1.f + __expf(-v));
                    int hh = col / 384, rem = col - hh * 384;
                    int t = rem >> 7, d = rem & 127;
                    int bi = row >> 12, s = row & 4095;
                    size_t dst = ((size_t)(bi * HEADS + hh) * SEQL + s) * HDIM + d;
                    __half* base = (t == 0) ? g_qh : (t == 1) ? g_kh : g_vh;
                    base[dst] = __float2half(sv);
                } else if (EPI == 1) {
                    size_t i = (size_t)row * HID + col;
                    g_gated[i] = __float2half(g_attn[i] / (1.f + __expf(-v)));
                } else {
                    Cout[(size_t)row * HID + col] = v;
                }
            }
}

// ------- per-block KV^T[e][d] = sum_n kdec[n] v[n,e] k[n,d]  (fp16 mma) -----
__global__ void __launch_bounds__(256) kv_outer_h() {
    const int blk = blockIdx.x, bh = blockIdx.y, h = bh & 31;
    const float slope = head_slope(h);
    __shared__ uint32_t Vsm[128][20];  // [e][n half2-words]
    __shared__ uint32_t Ksm[128][20];  // [d][n half2-words]
    const int tid = threadIdx.x, lane = tid & 31, w = tid >> 5;
    const int wm = w & 1, wn = w >> 1;

    float acc[4][4][4];
#pragma unroll
    for (int i = 0; i < 4; i++)
#pragma unroll
        for (int j = 0; j < 4; j++)
#pragma unroll
            for (int r = 0; r < 4; r++) acc[i][j][r] = 0.f;

    const size_t base = ((size_t)bh * SEQL + blk * BLKS) * HDIM;
    const int nl = tid & 31, qq = tid >> 5;
    for (int c = 0; c < 8; c++) {
        __syncthreads();
        int n = c * 32 + nl;
        float kd = __expf(-slope * (float)(255 - n));
#pragma unroll
        for (int r = 0; r < 2; r++) {
            int q = qq + 8 * r;                      // uint4 index 0..15
            uint4 k4 = *(const uint4*)(g_kh + base + (size_t)n * HDIM + q * 8);
            uint4 v4 = *(const uint4*)(g_vh + base + (size_t)n * HDIM + q * 8);
            const __half* kh = (const __half*)&k4;
            const __half* vh = (const __half*)&v4;
#pragma unroll
            for (int j = 0; j < 8; j++) {
                int d = q * 8 + j;
                ((__half*)&Ksm[d][nl >> 1])[nl & 1] = __float2half(__half2float(kh[j]) * kd);
                ((__half*)&Vsm[d][nl >> 1])[nl & 1] = vh[j];
            }
        }
        __syncthreads();
#pragma unroll
        for (int kk = 0; kk < 2; kk++) {
            int kq = kk * 8 + (lane & 3);
            uint32_t a[4][4], bb[4][2];
#pragma unroll
            for (int mi = 0; mi < 4; mi++) {
                int e = wm * 64 + mi * 16 + (lane >> 2);
                a[mi][0] = Vsm[e][kq];     a[mi][1] = Vsm[e + 8][kq];
                a[mi][2] = Vsm[e][kq + 4]; a[mi][3] = Vsm[e + 8][kq + 4];
            }
#pragma unroll
            for (int ni = 0; ni < 4; ni++) {
                int d = wn * 32 + ni * 8 + (lane >> 2);
                bb[ni][0] = Ksm[d][kq]; bb[ni][1] = Ksm[d][kq + 4];
            }
#pragma unroll
            for (int mi = 0; mi < 4; mi++)
#pragma unroll
                for (int ni = 0; ni < 4; ni++) mma16(acc[mi][ni], a[mi], bb[ni]);
        }
    }
    size_t ob = ((size_t)bh * NBLK + blk) * 16384;
#pragma unroll
    for (int mi = 0; mi < 4; mi++)
#pragma unroll
        for (int ni = 0; ni < 4; ni++)
#pragma unroll
            for (int r2 = 0; r2 < 4; r2++) {
                int e = wm * 64 + mi * 16 + (lane >> 2) + ((r2 >> 1) << 3);
                int d = wn * 32 + ni * 8 + ((lane & 3) << 1) + (r2 & 1);
                g_kv[ob + (size_t)e * HDIM + d] = acc[mi][ni][r2];
            }
}

// ---- scan over blocks (fp32): g_kv[bh][j] := decayed state BEFORE block j --
__global__ void __launch_bounds__(256) kv_scan() {
    const int bh = blockIdx.x, h = bh & 31;
    const float bdec = __expf(-head_slope(h) * 256.f);
    const size_t base = (size_t)bh * NBLK * 16384;
    float st[64];
#pragma unroll
    for (int i = 0; i < 64; i++) st[i] = 0.f;
    for (int j = 0; j < NBLK; j++) {
        size_t o = base + (size_t)j * 16384 + threadIdx.x;
#pragma unroll
        for (int i = 0; i < 64; i++) {
            float s = g_kv[o + i * 256];
            g_kv[o + i * 256] = st[i];
            st[i] = st[i] * bdec + s;
        }
    }
}

// ---------- attention: inter = (q@KV^T)*qdec  +  causal intra ---------------
// words: Qs[128][68] | region2 (KVs[128][68]  OR  Ks[32][68]+Vs[128][20]+Ss[128][20])
#define ATTN_SMEM 69632
__global__ void __launch_bounds__(256) attn_blk_h() {
    extern __shared__ uint32_t sm[];
    uint32_t (*Qs)[68]  = (uint32_t(*)[68])sm;
    uint32_t (*KVs)[68] = (uint32_t(*)[68])(sm + 8704);
    uint32_t (*Ks)[68]  = (uint32_t(*)[68])(sm + 8704);
    uint32_t (*Vs)[20]  = (uint32_t(*)[20])(sm + 10880);
    uint32_t (*Ss)[20]  = (uint32_t(*)[20])(sm + 13440);

    const int m0 = blockIdx.x * 128, blk = blockIdx.y, bh = blockIdx.z;
    const int b = bh >> 5, h = bh & 31;
    const float slope = head_slope(h);
    const int tid = threadIdx.x, lane = tid & 31, w = tid >> 5;
    const int wm = w & 1, wn = w >> 1;

    // load Q tile: 128 rows x 128 halves
    const size_t qb = ((size_t)bh * SEQL + blk * BLKS + m0) * HDIM;
#pragma unroll
    for (int r = 0; r < 8; r++) {
        int idx = tid + 256 * r, row = idx >> 4, q = idx & 15;
        *(uint4*)&Qs[row][q * 4] = *(const uint4*)(g_qh + qb + (size_t)row * HDIM + q * 8);
    }
    // load KV state [e][d] fp32 -> half
    const size_t kvb = ((size_t)bh * NBLK + blk) * 16384;
#pragma unroll
    for (int r = 0; r < 16; r++) {
        int idx = tid + 256 * r, e = idx >> 5, fq = idx & 31;
        float4 t = *(const float4*)(g_kv + kvb + (size_t)e * HDIM + fq * 4);
        *(__half2*)&KVs[e][fq * 2]     = __floats2half2_rn(t.x, t.y);
        *(__half2*)&KVs[e][fq * 2 + 1] = __floats2half2_rn(t.z, t.w);
    }
    __syncthreads();

    float acc[4][4][4];
#pragma unroll
    for (int i = 0; i < 4; i++)
#pragma unroll
        for (int j = 0; j < 4; j++)
#pragma unroll
            for (int r = 0; r < 4; r++) acc[i][j][r] = 0.f;

    // phase 1: inter[s][e] = sum_d q[s][d] KV^T[e][d]
#pragma unroll
    for (int kk = 0; kk < 8; kk++) {
        int kq = kk * 8 + (lane & 3);
        uint32_t a[4][4], bb[4][2];
#pragma unroll
        for (int mi = 0; mi < 4; mi++) {
            int r = wm * 64 + mi * 16 + (lane >> 2);
            a[mi][0] = Qs[r][kq];     a[mi][1] = Qs[r + 8][kq];
            a[mi][2] = Qs[r][kq + 4]; a[mi][3] = Qs[r + 8][kq + 4];
        }
#pragma unroll
        for (int ni = 0; ni < 4; ni++) {
            int e = wn * 32 + ni * 8 + (lane >> 2);
            bb[ni][0] = KVs[e][kq]; bb[ni][1] = KVs[e][kq + 4];
        }
#pragma unroll
        for (int mi = 0; mi < 4; mi++)
#pragma unroll
            for (int ni = 0; ni < 4; ni++) mma16(acc[mi][ni], a[mi], bb[ni]);
    }
    // scale by q_decay
#pragma unroll
    for (int mi = 0; mi < 4; mi++) {
        int r = wm * 64 + mi * 16 + (lane >> 2);
        float d0 = __expf(-slope * (float)(m0 + r + 1));
        float d1 = __expf(-slope * (float)(m0 + r + 9));
#pragma unroll
        for (int ni = 0; ni < 4; ni++) {
            acc[mi][ni][0] *= d0; acc[mi][ni][1] *= d0;
            acc[mi][ni][2] *= d1; acc[mi][ni][3] *= d1;
        }
    }

    // phase 2: intra over 32-wide key chunks
    const size_t kb0 = ((size_t)bh * SEQL + blk * BLKS) * HDIM;
    const int nch = (m0 >> 5) + 4;
    const int nl = tid & 31, qq = tid >> 5;
    for (int ch = 0; ch < nch; ch++) {
        int mc = ch * 32;
        __syncthreads();
        {   // K chunk [m][d]: 32 rows x 128 halves
#pragma unroll
            for (int r = 0; r < 2; r++) {
                int idx = tid + 256 * r, m = idx >> 4, q = idx & 15;
                *(uint4*)&Ks[m][q * 4] =
                    *(const uint4*)(g_kh + kb0 + (size_t)(mc + m) * HDIM + q * 8);
            }
            // V chunk transposed -> Vs[e][m-words]
#pragma unroll
            for (int r = 0; r < 2; r++) {
                int q2 = qq + 8 * r;
                uint4 v4 = *(const uint4*)(g_vh + kb0 + (size_t)(mc + nl) * HDIM + q2 * 8);
                const __half* vh = (const __half*)&v4;
#pragma unroll
                for (int j = 0; j < 8; j++) {
                    int e = q2 * 8 + j;
                    ((__half*)&Vs[e][nl >> 1])[nl & 1] = vh[j];
                }
            }
        }
        __syncthreads();
        // S = q @ k^T   (128 x 32)
        float sa[4][4];
#pragma unroll
        for (int mi = 0; mi < 4; mi++)
#pragma unroll
            for (int r2 = 0; r2 < 4; r2++) sa[mi][r2] = 0.f;
#pragma unroll
        for (int kk = 0; kk < 8; kk++) {
            int kq = kk * 8 + (lane & 3);
            uint32_t a[4][4], bb[2];
#pragma unroll
            for (int mi = 0; mi < 4; mi++) {
                int r = wm * 64 + mi * 16 + (lane >> 2);
                a[mi][0] = Qs[r][kq];     a[mi][1] = Qs[r + 8][kq];
                a[mi][2] = Qs[r][kq + 4]; a[mi][3] = Qs[r + 8][kq + 4];
            }
            int mcol = wn * 8 + (lane >> 2);
            bb[0] = Ks[mcol][kq]; bb[1] = Ks[mcol][kq + 4];
#pragma unroll
            for (int mi = 0; mi < 4; mi++) mma16(sa[mi], a[mi], bb);
        }
        // decay mask -> Ss (half2 packed, m even/odd)
#pragma unroll
        for (int mi = 0; mi < 4; mi++) {
            int me = wn * 8 + (lane & 3) * 2;
#pragma unroll
            for (int hf = 0; hf < 2; hf++) {
                int n = wm * 64 + mi * 16 + (lane >> 2) + hf * 8;
                int N = m0 + n;
                int M0 = mc + me, M1 = mc + me + 1;
                float v0 = (N >= M0) ? sa[mi][hf * 2]     * __expf(-slope * (float)(N - M0)) : 0.f;
                float v1 = (N >= M1) ? sa[mi][hf * 2 + 1] * __expf(-slope * (float)(N - M1)) : 0.f;
                *(__half2*)&Ss[n][wn * 4 + (lane & 3)] = __floats2half2_rn(v0, v1);
            }
        }
        __syncthreads();
        // out += Ss @ V   (contract over m=32)
#pragma unroll
        for (int kk = 0; kk < 2; kk++) {
            int kq = kk * 8 + (lane & 3);
            uint32_t a[4][4], bb[4][2];
#pragma unroll
            for (int mi = 0; mi < 4; mi++) {
                int r = wm * 64 + mi * 16 + (lane >> 2);
                a[mi][0] = Ss[r][kq];     a[mi][1] = Ss[r + 8][kq];
                a[mi][2] = Ss[r][kq + 4]; a[mi][3] = Ss[r + 8][kq + 4];
            }
#pragma unroll
            for (int ni = 0; ni < 4; ni++) {
                int e = wn * 32 + ni * 8 + (lane >> 2);
                bb[ni][0] = Vs[e][kq]; bb[ni][1] = Vs[e][kq + 4];
            }
#pragma unroll
            for (int mi = 0; mi < 4; mi++)
#pragma unroll
                for (int ni = 0; ni < 4; ni++) mma16(acc[mi][ni], a[mi], bb[ni]);
        }
    }

    const size_t ob = ((size_t)b * SEQL + blk * BLKS + m0) * HID + h * HDIM;
#pragma unroll
    for (int mi = 0; mi < 4; mi++)
#pragma unroll
        for (int ni = 0; ni < 4; ni++)
#pragma unroll
            for (int r2 = 0; r2 < 4; r2++) {
                int n = wm * 64 + mi * 16 + (lane >> 2) + ((r2 >> 1) << 3);
                int e = wn * 32 + ni * 8 + ((lane & 3) << 1) + (r2 & 1);
                g_attn[ob + (size_t)n * HID + e] = acc[mi][ni][r2];
            }
}

// ------------------------------ RMSNorm (fp32) ------------------------------
__global__ void __launch_bounds__(256) rmsnorm(const float* __restrict__ nw) {
    const size_t base = (size_t)blockIdx.x * HID;
    const int tid = threadIdx.x;
    float4 x[4];
    float ss = 0.f;
#pragma unroll
    for (int j = 0; j < 4; j++) {
        x[j] = *(const float4*)(g_attn + base + (size_t)(tid + 256 * j) * 4);
        ss += x[j].x * x[j].x + x[j].y * x[j].y + x[j].z * x[j].z + x[j].w * x[j].w;
    }
#pragma unroll
    for (int o = 16; o; o >>= 1) ss += __shfl_xor_sync(0xffffffffu, ss, o);
    __shared__ float sred[8];
    if ((tid & 31) == 0) sred[tid >> 5] = ss;
    __syncthreads();
    float tot = 0.f;
#pragma unroll
    for (int i = 0; i < 8; i++) tot += sred[i];
    float sc = rsqrtf(tot * (1.f / 4096.f) + 1e-5f);
#pragma unroll
    for (int j = 0; j < 4; j++) {
        int col = (tid + 256 * j) * 4;
        float4 o4;
        o4.x = x[j].x * sc * nw[col];     o4.y = x[j].y * sc * nw[col + 1];
        o4.z = x[j].z * sc * nw[col + 2]; o4.w = x[j].w * sc * nw[col + 3];
        *(float4*)(g_attn + base + col) = o4;
    }
}

// --------------------------------- launch -----------------------------------
extern "C" void kernel_launch(void* const* d_in, const int* in_sizes, int n_in,
                              void* d_out, int out_size) {
    const float* X    = (const float*)d_in[0];
    const float* Wqkv = (const float*)d_in[1];
    const float* Wo   = (const float*)d_in[2];
    const float* Wg   = (const float*)d_in[3];
    const float* nw   = (const float*)d_in[4];
    float* out = (float*)d_out;

    cudaFuncSetAttribute(gemm_h<0>, cudaFuncAttributeMaxDynamicSharedMemorySize, GEMM_SMEM);
    cudaFuncSetAttribute(gemm_h<1>, cudaFuncAttributeMaxDynamicSharedMemorySize, GEMM_SMEM);
    cudaFuncSetAttribute(gemm_h<2>, cudaFuncAttributeMaxDynamicSharedMemorySize, GEMM_SMEM);
    cudaFuncSetAttribute(attn_blk_h, cudaFuncAttributeMaxDynamicSharedMemorySize, ATTN_SMEM);

    f2h<0><<<32768, 256>>>(X, 8388608);
    f2h<1><<<49152, 256>>>(Wqkv, 12582912);
    f2h<2><<<16384, 256>>>(Wg, 4194304);
    f2h<3><<<16384, 256>>>(Wo, 4194304);

    gemm_h<0><<<dim3(96, 64), 256, GEMM_SMEM>>>(nullptr);
    kv_outer_h<<<dim3(16, 64), 256>>>();
    kv_scan<<<64, 256>>>();
    attn_blk_h<<<dim3(2, 16, 64), 256, ATTN_SMEM>>>();
    rmsnorm<<<8192, 256>>>(nw);
    gemm_h<1><<<dim3(32, 64), 256, GEMM_SMEM>>>(nullptr);
    gemm_h<2><<<dim3(32, 64), 256, GEMM_SMEM>>>(out);
}

// round 14
// speedup vs baseline: 1.1702x; 1.1702x over previous
#include <cuda_runtime.h>
#include <cuda_fp16.h>
#include <cstdint>
#include <cstddef>

#define HEADS 32
#define HDIM  128
#define SEQL  4096
#define BLKS  256
#define NBLK  16
#define HID   4096
#define KDIM  4096

// fp16 operand buffers
__device__ __half g_xh[33554432];      // X           (b*s, 4096)
__device__ __half g_wqkvh[50331648];   // Wqkv        (12288, 4096)
__device__ __half g_wgh[16777216];     // Wg          (4096, 4096)
__device__ __half g_woh[16777216];     // Wo          (4096, 4096)
__device__ __half g_qh[33554432];      // (bh, s, d)
__device__ __half g_kh[33554432];
__device__ __half g_vh[33554432];
__device__ __half g_gated[33554432];   // sigmoid(gate)*normed (b*s, 4096)
// fp32 state
__device__ float  g_kv[16777216];      // (bh, blk, e, d)  [e-major = KV^T]
__device__ float  g_attn[33554432];    // (b, s, h*d)

__device__ __forceinline__ void mma16(float* c, const uint32_t* a, const uint32_t* b) {
    asm volatile("mma.sync.aligned.m16n8k16.row.col.f32.f16.f16.f32 "
        "{%0,%1,%2,%3},{%4,%5,%6,%7},{%8,%9},{%0,%1,%2,%3};\n"
        : "+f"(c[0]), "+f"(c[1]), "+f"(c[2]), "+f"(c[3])
        : "r"(a[0]), "r"(a[1]), "r"(a[2]), "r"(a[3]), "r"(b[0]), "r"(b[1]));
}
__device__ __forceinline__ void ldsm4(uint32_t& r0, uint32_t& r1, uint32_t& r2, uint32_t& r3,
                                      uint32_t addr) {
    asm volatile("ldmatrix.sync.aligned.m8n8.x4.shared.b16 {%0,%1,%2,%3}, [%4];"
        : "=r"(r0), "=r"(r1), "=r"(r2), "=r"(r3) : "r"(addr));
}
__device__ __forceinline__ float head_slope(int h) {
    float factor = 1.0f - 1.0f / (31.0f + 1e-5f) + 1e-5f;
    return exp2f(-0.25f * (float)(h + 1)) * factor;
}
__device__ __forceinline__ uint32_t s2u(const void* p) {
    return (uint32_t)__cvta_generic_to_shared(p);
}

// ----------------------- fp32 -> fp16 conversion ---------------------------
template <int DST>
__global__ void __launch_bounds__(256) f2h(const float* __restrict__ s, int n4) {
    int i = blockIdx.x * 256 + threadIdx.x;
    if (i >= n4) return;
    float4 v = ((const float4*)s)[i];
    __half* d = (DST == 0) ? g_xh : (DST == 1) ? g_wqkvh : (DST == 2) ? g_wgh : g_woh;
    ((__half2*)d)[i * 2]     = __floats2half2_rn(v.x, v.y);
    ((__half2*)d)[i * 2 + 1] = __floats2half2_rn(v.z, v.w);
}

// ------------- fp16 NT GEMM: C[m,n] = sum_k A[m,k] B[n,k], K=4096 ----------
// R8 register-prefetch double buffer + ldmatrix fragment loads.
// EPI 0: A=g_xh B=g_wqkvh, silu -> scatter q/k/v (half)
// EPI 1: A=g_xh B=g_wgh,   g_gated = half(sigmoid(C)*g_attn)
// EPI 2: A=g_gated B=g_woh, Cout = C (float)
template <int EPI>
__global__ void __launch_bounds__(256) gemm_h(float* __restrict__ Cout) {
    __shared__ uint32_t As[128][36];   // [m][k half2-words], BK=64 halves
    __shared__ uint32_t Bs[128][36];
    const int tid = threadIdx.x, lane = tid & 31, w = tid >> 5;
    const int wm = w & 1, wn = w >> 1;
    const int m0 = blockIdx.y * 128, n0 = blockIdx.x * 128;
    const __half* Ap = (EPI == 2) ? g_gated : g_xh;
    const __half* Bp = (EPI == 0) ? g_wqkvh : (EPI == 1) ? g_wgh : g_woh;

    // per-lane ldmatrix source coordinates
    const uint32_t aBase = s2u(As), bBase = s2u(Bs);
    const int aRow  = wm * 64 + (lane & 15);          // + mi*16
    const int aWOff = (lane >> 4) * 4;                // 0 | 4
    const int bRow  = wn * 32 + (lane & 7) + ((lane >> 4) << 3);  // + ni2*16
    const int bWOff = ((lane >> 3) & 1) * 4;          // 0 | 4

    float acc[4][4][4];
#pragma unroll
    for (int i = 0; i < 4; i++)
#pragma unroll
        for (int j = 0; j < 4; j++)
#pragma unroll
            for (int r = 0; r < 4; r++) acc[i][j][r] = 0.f;

    uint4 pa[4], pb[4];
#pragma unroll
    for (int r = 0; r < 4; r++) {
        int idx = tid + 256 * r, row = idx >> 3, q = idx & 7;
        pa[r] = *(const uint4*)(Ap + (size_t)(m0 + row) * KDIM + q * 8);
        pb[r] = *(const uint4*)(Bp + (size_t)(n0 + row) * KDIM + q * 8);
    }

    for (int k0 = 0; k0 < KDIM; k0 += 64) {
#pragma unroll
        for (int r = 0; r < 4; r++) {
            int idx = tid + 256 * r, row = idx >> 3, q = idx & 7;
            *(uint4*)&As[row][q * 4] = pa[r];
            *(uint4*)&Bs[row][q * 4] = pb[r];
        }
        __syncthreads();
        if (k0 + 64 < KDIM) {
#pragma unroll
            for (int r = 0; r < 4; r++) {
                int idx = tid + 256 * r, row = idx >> 3, q = idx & 7;
                pa[r] = *(const uint4*)(Ap + (size_t)(m0 + row) * KDIM + k0 + 64 + q * 8);
                pb[r] = *(const uint4*)(Bp + (size_t)(n0 + row) * KDIM + k0 + 64 + q * 8);
            }
        }
#pragma unroll
        for (int kk = 0; kk < 4; kk++) {
            uint32_t a[4][4], bb[4][2];
#pragma unroll
            for (int mi = 0; mi < 4; mi++)
                ldsm4(a[mi][0], a[mi][1], a[mi][2], a[mi][3],
                      aBase + (((aRow + mi * 16) * 36 + kk * 8 + aWOff) << 2));
#pragma unroll
            for (int ni2 = 0; ni2 < 2; ni2++)
                ldsm4(bb[ni2 * 2][0], bb[ni2 * 2][1], bb[ni2 * 2 + 1][0], bb[ni2 * 2 + 1][1],
                      bBase + (((bRow + ni2 * 16) * 36 + kk * 8 + bWOff) << 2));
#pragma unroll
            for (int mi = 0; mi < 4; mi++)
#pragma unroll
                for (int ni = 0; ni < 4; ni++) mma16(acc[mi][ni], a[mi], bb[ni]);
        }
        __syncthreads();
    }

#pragma unroll
    for (int mi = 0; mi < 4; mi++)
#pragma unroll
        for (int ni = 0; ni < 4; ni++)
#pragma unroll
            for (int r2 = 0; r2 < 4; r2++) {
                int row = m0 + wm * 64 + mi * 16 + (lane >> 2) + ((r2 >> 1) << 3);
                int col = n0 + wn * 32 + ni * 8 + ((lane & 3) << 1) + (r2 & 1);
                float v = acc[mi][ni][r2];
                if (EPI == 0) {
                    float sv = v / (1.f + __expf(-v));
                    int hh = col / 384, rem = col - hh * 384;
                    int t = rem >> 7, d = rem & 127;
                    int bi = row >> 12, s = row & 4095;
                    size_t dst = ((size_t)(bi * HEADS + hh) * SEQL + s) * HDIM + d;
                    __half* base = (t == 0) ? g_qh : (t == 1) ? g_kh : g_vh;
                    base[dst] = __float2half(sv);
                } else if (EPI == 1) {
                    size_t i = (size_t)row * HID + col;
                    g_gated[i] = __float2half(g_attn[i] / (1.f + __expf(-v)));
                } else {
                    Cout[(size_t)row * HID + col] = v;
                }
            }
}

// ------- per-block KV^T[e][d] = sum_n kdec[n] v[n,e] k[n,d]  (fp16 mma) -----
__global__ void __launch_bounds__(256) kv_outer_h() {
    const int blk = blockIdx.x, bh = blockIdx.y, h = bh & 31;
    const float slope = head_slope(h);
    __shared__ uint32_t Vsm[128][20];  // [e][n half2-words]
    __shared__ uint32_t Ksm[128][20];  // [d][n half2-words]
    const int tid = threadIdx.x, lane = tid & 31, w = tid >> 5;
    const int wm = w & 1, wn = w >> 1;

    float acc[4][4][4];
#pragma unroll
    for (int i = 0; i < 4; i++)
#pragma unroll
        for (int j = 0; j < 4; j++)
#pragma unroll
            for (int r = 0; r < 4; r++) acc[i][j][r] = 0.f;

    const size_t base = ((size_t)bh * SEQL + blk * BLKS) * HDIM;
    const int nl = tid & 31, qq = tid >> 5;
    for (int c = 0; c < 8; c++) {
        __syncthreads();
        int n = c * 32 + nl;
        float kd = __expf(-slope * (float)(255 - n));
#pragma unroll
        for (int r = 0; r < 2; r++) {
            int q = qq + 8 * r;                      // uint4 index 0..15
            uint4 k4 = *(const uint4*)(g_kh + base + (size_t)n * HDIM + q * 8);
            uint4 v4 = *(const uint4*)(g_vh + base + (size_t)n * HDIM + q * 8);
            const __half* kh = (const __half*)&k4;
            const __half* vh = (const __half*)&v4;
#pragma unroll
            for (int j = 0; j < 8; j++) {
                int d = q * 8 + j;
                ((__half*)&Ksm[d][nl >> 1])[nl & 1] = __float2half(__half2float(kh[j]) * kd);
                ((__half*)&Vsm[d][nl >> 1])[nl & 1] = vh[j];
            }
        }
        __syncthreads();
#pragma unroll
        for (int kk = 0; kk < 2; kk++) {
            int kq = kk * 8 + (lane & 3);
            uint32_t a[4][4], bb[4][2];
#pragma unroll
            for (int mi = 0; mi < 4; mi++) {
                int e = wm * 64 + mi * 16 + (lane >> 2);
                a[mi][0] = Vsm[e][kq];     a[mi][1] = Vsm[e + 8][kq];
                a[mi][2] = Vsm[e][kq + 4]; a[mi][3] = Vsm[e + 8][kq + 4];
            }
#pragma unroll
            for (int ni = 0; ni < 4; ni++) {
                int d = wn * 32 + ni * 8 + (lane >> 2);
                bb[ni][0] = Ksm[d][kq]; bb[ni][1] = Ksm[d][kq + 4];
            }
#pragma unroll
            for (int mi = 0; mi < 4; mi++)
#pragma unroll
                for (int ni = 0; ni < 4; ni++) mma16(acc[mi][ni], a[mi], bb[ni]);
        }
    }
    size_t ob = ((size_t)bh * NBLK + blk) * 16384;
#pragma unroll
    for (int mi = 0; mi < 4; mi++)
#pragma unroll
        for (int ni = 0; ni < 4; ni++)
#pragma unroll
            for (int r2 = 0; r2 < 4; r2++) {
                int e = wm * 64 + mi * 16 + (lane >> 2) + ((r2 >> 1) << 3);
                int d = wn * 32 + ni * 8 + ((lane & 3) << 1) + (r2 & 1);
                g_kv[ob + (size_t)e * HDIM + d] = acc[mi][ni][r2];
            }
}

// ---- scan over blocks (fp32): g_kv[bh][j] := decayed state BEFORE block j --
__global__ void __launch_bounds__(256) kv_scan() {
    const int bh = blockIdx.x, h = bh & 31;
    const float bdec = __expf(-head_slope(h) * 256.f);
    const size_t base = (size_t)bh * NBLK * 16384;
    float st[64];
#pragma unroll
    for (int i = 0; i < 64; i++) st[i] = 0.f;
    for (int j = 0; j < NBLK; j++) {
        size_t o = base + (size_t)j * 16384 + threadIdx.x;
#pragma unroll
        for (int i = 0; i < 64; i++) {
            float s = g_kv[o + i * 256];
            g_kv[o + i * 256] = st[i];
            st[i] = st[i] * bdec + s;
        }
    }
}

// ---------- attention: inter = (q@KV^T)*qdec  +  causal intra ---------------
// words: Qs[128][68] | region2 (KVs[128][68]  OR  Ks[32][68]+Vs[128][20]+Ss[128][20])
#define ATTN_SMEM 69632
__global__ void __launch_bounds__(256) attn_blk_h() {
    extern __shared__ uint32_t sm[];
    uint32_t (*Qs)[68]  = (uint32_t(*)[68])sm;
    uint32_t (*KVs)[68] = (uint32_t(*)[68])(sm + 8704);
    uint32_t (*Ks)[68]  = (uint32_t(*)[68])(sm + 8704);
    uint32_t (*Vs)[20]  = (uint32_t(*)[20])(sm + 10880);
    uint32_t (*Ss)[20]  = (uint32_t(*)[20])(sm + 13440);

    const int m0 = blockIdx.x * 128, blk = blockIdx.y, bh = blockIdx.z;
    const int b = bh >> 5, h = bh & 31;
    const float slope = head_slope(h);
    const int tid = threadIdx.x, lane = tid & 31, w = tid >> 5;
    const int wm = w & 1, wn = w >> 1;

    // load Q tile: 128 rows x 128 halves
    const size_t qb = ((size_t)bh * SEQL + blk * BLKS + m0) * HDIM;
#pragma unroll
    for (int r = 0; r < 8; r++) {
        int idx = tid + 256 * r, row = idx >> 4, q = idx & 15;
        *(uint4*)&Qs[row][q * 4] = *(const uint4*)(g_qh + qb + (size_t)row * HDIM + q * 8);
    }
    // load KV state [e][d] fp32 -> half
    const size_t kvb = ((size_t)bh * NBLK + blk) * 16384;
#pragma unroll
    for (int r = 0; r < 16; r++) {
        int idx = tid + 256 * r, e = idx >> 5, fq = idx & 31;
        float4 t = *(const float4*)(g_kv + kvb + (size_t)e * HDIM + fq * 4);
        *(__half2*)&KVs[e][fq * 2]     = __floats2half2_rn(t.x, t.y);
        *(__half2*)&KVs[e][fq * 2 + 1] = __floats2half2_rn(t.z, t.w);
    }
    __syncthreads();

    float acc[4][4][4];
#pragma unroll
    for (int i = 0; i < 4; i++)
#pragma unroll
        for (int j = 0; j < 4; j++)
#pragma unroll
            for (int r = 0; r < 4; r++) acc[i][j][r] = 0.f;

    // phase 1: inter[s][e] = sum_d q[s][d] KV^T[e][d]
#pragma unroll
    for (int kk = 0; kk < 8; kk++) {
        int kq = kk * 8 + (lane & 3);
        uint32_t a[4][4], bb[4][2];
#pragma unroll
        for (int mi = 0; mi < 4; mi++) {
            int r = wm * 64 + mi * 16 + (lane >> 2);
            a[mi][0] = Qs[r][kq];     a[mi][1] = Qs[r + 8][kq];
            a[mi][2] = Qs[r][kq + 4]; a[mi][3] = Qs[r + 8][kq + 4];
        }
#pragma unroll
        for (int ni = 0; ni < 4; ni++) {
            int e = wn * 32 + ni * 8 + (lane >> 2);
            bb[ni][0] = KVs[e][kq]; bb[ni][1] = KVs[e][kq + 4];
        }
#pragma unroll
        for (int mi = 0; mi < 4; mi++)
#pragma unroll
            for (int ni = 0; ni < 4; ni++) mma16(acc[mi][ni], a[mi], bb[ni]);
    }
    // scale by q_decay
#pragma unroll
    for (int mi = 0; mi < 4; mi++) {
        int r = wm * 64 + mi * 16 + (lane >> 2);
        float d0 = __expf(-slope * (float)(m0 + r + 1));
        float d1 = __expf(-slope * (float)(m0 + r + 9));
#pragma unroll
        for (int ni = 0; ni < 4; ni++) {
            acc[mi][ni][0] *= d0; acc[mi][ni][1] *= d0;
            acc[mi][ni][2] *= d1; acc[mi][ni][3] *= d1;
        }
    }

    // phase 2: intra over 32-wide key chunks
    const size_t kb0 = ((size_t)bh * SEQL + blk * BLKS) * HDIM;
    const int nch = (m0 >> 5) + 4;
    const int nl = tid & 31, qq = tid >> 5;
    for (int ch = 0; ch < nch; ch++) {
        int mc = ch * 32;
        __syncthreads();
        {   // K chunk [m][d]: 32 rows x 128 halves
#pragma unroll
            for (int r = 0; r < 2; r++) {
                int idx = tid + 256 * r, m = idx >> 4, q = idx & 15;
                *(uint4*)&Ks[m][q * 4] =
                    *(const uint4*)(g_kh + kb0 + (size_t)(mc + m) * HDIM + q * 8);
            }
            // V chunk transposed -> Vs[e][m-words]
#pragma unroll
            for (int r = 0; r < 2; r++) {
                int q2 = qq + 8 * r;
                uint4 v4 = *(const uint4*)(g_vh + kb0 + (size_t)(mc + nl) * HDIM + q2 * 8);
                const __half* vh = (const __half*)&v4;
#pragma unroll
                for (int j = 0; j < 8; j++) {
                    int e = q2 * 8 + j;
                    ((__half*)&Vs[e][nl >> 1])[nl & 1] = vh[j];
                }
            }
        }
        __syncthreads();
        // S = q @ k^T   (128 x 32)
        float sa[4][4];
#pragma unroll
        for (int mi = 0; mi < 4; mi++)
#pragma unroll
            for (int r2 = 0; r2 < 4; r2++) sa[mi][r2] = 0.f;
#pragma unroll
        for (int kk = 0; kk < 8; kk++) {
            int kq = kk * 8 + (lane & 3);
            uint32_t a[4][4], bb[2];
#pragma unroll
            for (int mi = 0; mi < 4; mi++) {
                int r = wm * 64 + mi * 16 + (lane >> 2);
                a[mi][0] = Qs[r][kq];     a[mi][1] = Qs[r + 8][kq];
                a[mi][2] = Qs[r][kq + 4]; a[mi][3] = Qs[r + 8][kq + 4];
            }
            int mcol = wn * 8 + (lane >> 2);
            bb[0] = Ks[mcol][kq]; bb[1] = Ks[mcol][kq + 4];
#pragma unroll
            for (int mi = 0; mi < 4; mi++) mma16(sa[mi], a[mi], bb);
        }
        // decay mask -> Ss (half2 packed, m even/odd)
#pragma unroll
        for (int mi = 0; mi < 4; mi++) {
            int me = wn * 8 + (lane & 3) * 2;
#pragma unroll
            for (int hf = 0; hf < 2; hf++) {
                int n = wm * 64 + mi * 16 + (lane >> 2) + hf * 8;
                int N = m0 + n;
                int M0 = mc + me, M1 = mc + me + 1;
                float v0 = (N >= M0) ? sa[mi][hf * 2]     * __expf(-slope * (float)(N - M0)) : 0.f;
                float v1 = (N >= M1) ? sa[mi][hf * 2 + 1] * __expf(-slope * (float)(N - M1)) : 0.f;
                *(__half2*)&Ss[n][wn * 4 + (lane & 3)] = __floats2half2_rn(v0, v1);
            }
        }
        __syncthreads();
        // out += Ss @ V   (contract over m=32)
#pragma unroll
        for (int kk = 0; kk < 2; kk++) {
            int kq = kk * 8 + (lane & 3);
            uint32_t a[4][4], bb[4][2];
#pragma unroll
            for (int mi = 0; mi < 4; mi++) {
                int r = wm * 64 + mi * 16 + (lane >> 2);
                a[mi][0] = Ss[r][kq];     a[mi][1] = Ss[r + 8][kq];
                a[mi][2] = Ss[r][kq + 4]; a[mi][3] = Ss[r + 8][kq + 4];
            }
#pragma unroll
            for (int ni = 0; ni < 4; ni++) {
                int e = wn * 32 + ni * 8 + (lane >> 2);
                bb[ni][0] = Vs[e][kq]; bb[ni][1] = Vs[e][kq + 4];
            }
#pragma unroll
            for (int mi = 0; mi < 4; mi++)
#pragma unroll
                for (int ni = 0; ni < 4; ni++) mma16(acc[mi][ni], a[mi], bb[ni]);
        }
    }

    const size_t ob = ((size_t)b * SEQL + blk * BLKS + m0) * HID + h * HDIM;
#pragma unroll
    for (int mi = 0; mi < 4; mi++)
#pragma unroll
        for (int ni = 0; ni < 4; ni++)
#pragma unroll
            for (int r2 = 0; r2 < 4; r2++) {
                int n = wm * 64 + mi * 16 + (lane >> 2) + ((r2 >> 1) << 3);
                int e = wn * 32 + ni * 8 + ((lane & 3) << 1) + (r2 & 1);
                g_attn[ob + (size_t)n * HID + e] = acc[mi][ni][r2];
            }
}

// ------------------------------ RMSNorm (fp32) ------------------------------
__global__ void __launch_bounds__(256) rmsnorm(const float* __restrict__ nw) {
    const size_t base = (size_t)blockIdx.x * HID;
    const int tid = threadIdx.x;
    float4 x[4];
    float ss = 0.f;
#pragma unroll
    for (int j = 0; j < 4; j++) {
        x[j] = *(const float4*)(g_attn + base + (size_t)(tid + 256 * j) * 4);
        ss += x[j].x * x[j].x + x[j].y * x[j].y + x[j].z * x[j].z + x[j].w * x[j].w;
    }
#pragma unroll
    for (int o = 16; o; o >>= 1) ss += __shfl_xor_sync(0xffffffffu, ss, o);
    __shared__ float sred[8];
    if ((tid & 31) == 0) sred[tid >> 5] = ss;
    __syncthreads();
    float tot = 0.f;
#pragma unroll
    for (int i = 0; i < 8; i++) tot += sred[i];
    float sc = rsqrtf(tot * (1.f / 4096.f) + 1e-5f);
#pragma unroll
    for (int j = 0; j < 4; j++) {
        int col = (tid + 256 * j) * 4;
        float4 o4;
        o4.x = x[j].x * sc * nw[col];     o4.y = x[j].y * sc * nw[col + 1];
        o4.z = x[j].z * sc * nw[col + 2]; o4.w = x[j].w * sc * nw[col + 3];
        *(float4*)(g_attn + base + col) = o4;
    }
}

// --------------------------------- launch -----------------------------------
extern "C" void kernel_launch(void* const* d_in, const int* in_sizes, int n_in,
                              void* d_out, int out_size) {
    const float* X    = (const float*)d_in[0];
    const float* Wqkv = (const float*)d_in[1];
    const float* Wo   = (const float*)d_in[2];
    const float* Wg   = (const float*)d_in[3];
    const float* nw   = (const float*)d_in[4];
    float* out = (float*)d_out;

    cudaFuncSetAttribute(attn_blk_h, cudaFuncAttributeMaxDynamicSharedMemorySize, ATTN_SMEM);

    f2h<0><<<32768, 256>>>(X, 8388608);
    f2h<1><<<49152, 256>>>(Wqkv, 12582912);
    f2h<2><<<16384, 256>>>(Wg, 4194304);
    f2h<3><<<16384, 256>>>(Wo, 4194304);

    gemm_h<0><<<dim3(96, 64), 256>>>(nullptr);
    kv_outer_h<<<dim3(16, 64), 256>>>();
    kv_scan<<<64, 256>>>();
    attn_blk_h<<<dim3(2, 16, 64), 256, ATTN_SMEM>>>();
    rmsnorm<<<8192, 256>>>(nw);
    gemm_h<1><<<dim3(32, 64), 256>>>(nullptr);
    gemm_h<2><<<dim3(32, 64), 256>>>(out);
}